// round 14
// baseline (speedup 1.0000x reference)
#include <cuda_runtime.h>
#include <cuda_fp16.h>
#include <math.h>

// Problem shape (fixed): B=8, C=4, H=256, W=256, labels in [0,4)
#define B 8
#define H 256
#define W 256
#define NPIX (B * H * W)          // 524288
#define NROWS (B * H)             // 2048
#define NBLK2 (NROWS / 2)         // 1024 k_horiz blocks (2 rows each)
#define DENOM 2097152.0           // B*C*H*W
#define FPSCALE 16777216.0        // 2^24 fixed-point scale
#define HBIG 65504.0f             // half max: absent-class sentinel

// Column occupancy bitmasks: g_M[((b*4 + c)*8 + j)*256 + w], bit (r&31) of
// word j = (label(b, r, w) == c) for r = j*32..j*32+31.  256 KB: L2-resident.
__device__ unsigned g_M[B * 4 * 8 * W];
__device__ unsigned long long g_acc;         // fixed-point loss accumulator (zero-init)
__device__ unsigned int g_count;             // completed-block counter (zero-init)

__device__ __forceinline__ float fsqrt_fast(float v)
{
    float r;
    asm("sqrt.approx.f32 %0, %1;" : "=f"(r) : "f"(v));
    return r;
}

// Exact vertical nearest-feature distance for row r in the column mask cm
// (words at stride 256). Inclusive both directions (d=0 at feature pixels).
__device__ __forceinline__ int vdist(const unsigned* __restrict__ cm, int r)
{
    const int jr = r >> 5, hb = r & 31;
    const unsigned Mw = cm[jr * 256];
    unsigned down = Mw & (0xffffffffu >> (31 - hb));   // bits 0..hb of word jr
    unsigned up   = Mw >> hb;                          // bits hb..31
    int dd = 1000, du = 1000;
    if (down) {
        dd = hb - (31 - __clz(down));
    } else {
        for (int j = jr - 1; j >= 0; --j) {
            unsigned m = cm[j * 256];
            if (m) { dd = r - (j * 32 + 31 - __clz(m)); break; }
        }
    }
    if (up) {
        du = __ffs(up) - 1;
    } else {
        for (int j = jr + 1; j < 8; ++j) {
            unsigned m = cm[j * 256];
            if (m) { du = j * 32 + __ffs(m) - 1 - r; break; }
        }
    }
    return min(dd, du);
}

// ---------------------------------------------------------------------------
// K1: build per-column class occupancy masks (ballots only; no distances).
// 256 blocks x 256 threads: 8 columns per block, warp = word index (row/32).
// ---------------------------------------------------------------------------
__global__ void __launch_bounds__(256) k_mask(const int* __restrict__ y)
{
    const int b    = blockIdx.x >> 5;        // 256 blocks: 8 b * 32 w-tiles
    const int w0   = (blockIdx.x & 31) << 3; // 8 columns per block
    const int tid  = threadIdx.x;            // 256 threads = 8 warps
    const int warp = tid >> 5;               // = mask word index (row/32)
    const int lane = tid & 31;

    const int row = warp * 32 + lane;
    const int* yrow = y + b * (H * W) + row * W + w0;
    int4 va = *(const int4*)yrow;
    int4 vb = *(const int4*)(yrow + 4);
    int lab[8] = {va.x, va.y, va.z, va.w, vb.x, vb.y, vb.z, vb.w};

    unsigned myword = 0;
    #pragma unroll
    for (int c = 0; c < 4; ++c) {
        #pragma unroll
        for (int k = 0; k < 8; ++k) {
            unsigned bal = __ballot_sync(0xffffffffu, lab[k] == c);
            if (lane == ((c << 3) | k)) myword = bal;
        }
    }
    // lane encodes (c = lane>>3, k = lane&7); word index = warp
    g_M[(((b * 4) + (lane >> 3)) * 8 + warp) * 256 + w0 + (lane & 7)] = myword;
}

// ---------------------------------------------------------------------------
// K2: fused vertical-distance + horizontal min-plus, TWO ROWS PER BLOCK.
// Staging computes per-pixel vertical d^2 directly from the L2-resident
// masks (rows row0, row0+1 share the same mask word: row0 is even), packs
// to half2x2 in smem; then the round-12 adaptive scan + epilogue.
// ---------------------------------------------------------------------------
__global__ void __launch_bounds__(256) k_horiz(const float* __restrict__ x,
                                               const int* __restrict__ y,
                                               float* __restrict__ out)
{
    const int row0 = blockIdx.x * 2;   // rows row0, row0+1 (same image: H even)
    const int b    = row0 >> 8;
    const int h0r  = row0 & 255;       // even
    const int tid  = threadIdx.x;      // 0..255, w = tid
    const int wid  = tid >> 5, lane = tid & 31;

    __shared__ uint2 sgp0[768];        // row0: [pad 256][data 256][pad 256]
    __shared__ uint2 sgp1[768];        // row1
    uint2* sg0 = sgp0 + 256;
    uint2* sg1 = sgp1 + 256;

    // issue loads early — latency overlaps mask probing
    const int yv0 = y[row0 * W + tid];
    const int yv1 = y[(row0 + 1) * W + tid];
    const int base = (b * 4) * (H * W) + h0r * W + tid;
    float lx00 = x[base];
    float lx01 = x[base + H * W];
    float lx02 = x[base + 2 * H * W];
    float lx03 = x[base + 3 * H * W];
    float lx10 = x[base + W];
    float lx11 = x[base + W + H * W];
    float lx12 = x[base + W + 2 * H * W];
    float lx13 = x[base + W + 3 * H * W];

    const uint2 big = make_uint2(0x7BFF7BFFu, 0x7BFF7BFFu);  // half2(65504) x2
    sgp0[tid] = big;  sgp0[512 + tid] = big;
    sgp1[tid] = big;  sgp1[512 + tid] = big;

    // vertical distances from masks (coalesced: lanes = consecutive w)
    float f00, f01, f02, f03, f10, f11, f12, f13;
    {
        const unsigned* mb = g_M + (b * 4) * (8 * 256) + tid;  // class stride 2048
        #pragma unroll
        for (int c = 0; c < 4; ++c) {
            const unsigned* cm = mb + c * 2048;
            int d0 = vdist(cm, h0r);
            int d1 = vdist(cm, h0r + 1);
            float g0 = (d0 > 255) ? HBIG : (float)(d0 * d0);
            float g1 = (d1 > 255) ? HBIG : (float)(d1 * d1);
            if (c == 0) { f00 = g0; f10 = g1; }
            else if (c == 1) { f01 = g0; f11 = g1; }
            else if (c == 2) { f02 = g0; f12 = g1; }
            else { f03 = g0; f13 = g1; }
        }
    }

    __half2 ba0 = __floats2half2_rn(f00, f01);
    __half2 bb0 = __floats2half2_rn(f02, f03);
    __half2 ba1 = __floats2half2_rn(f10, f11);
    __half2 bb1 = __floats2half2_rn(f12, f13);
    {
        uint2 p0, p1;
        p0.x = *reinterpret_cast<unsigned*>(&ba0);
        p0.y = *reinterpret_cast<unsigned*>(&bb0);
        p1.x = *reinterpret_cast<unsigned*>(&ba1);
        p1.y = *reinterpret_cast<unsigned*>(&bb1);
        sg0[tid] = p0;
        sg1[tid] = p1;
    }
    __syncthreads();

    for (int off0 = 1; off0 < 256; off0 += 4) {
        #pragma unroll
        for (int u = 0; u < 4; ++u) {
            int off = off0 + u;                      // max 256 -> within pads
            __half2 o2 = __float2half2_rn((float)(off * off));
            uint2 l0 = sg0[tid - off];
            uint2 r0 = sg0[tid + off];
            uint2 l1 = sg1[tid - off];
            uint2 r1 = sg1[tid + off];
            __half2 la0 = *reinterpret_cast<__half2*>(&l0.x);
            __half2 lb0 = *reinterpret_cast<__half2*>(&l0.y);
            __half2 ra0 = *reinterpret_cast<__half2*>(&r0.x);
            __half2 rb0 = *reinterpret_cast<__half2*>(&r0.y);
            __half2 la1 = *reinterpret_cast<__half2*>(&l1.x);
            __half2 lb1 = *reinterpret_cast<__half2*>(&l1.y);
            __half2 ra1 = *reinterpret_cast<__half2*>(&r1.x);
            __half2 rb1 = *reinterpret_cast<__half2*>(&r1.y);
            ba0 = __hmin2(ba0, __hadd2(o2, __hmin2(la0, ra0)));
            bb0 = __hmin2(bb0, __hadd2(o2, __hmin2(lb0, rb0)));
            ba1 = __hmin2(ba1, __hadd2(o2, __hmin2(la1, ra1)));
            bb1 = __hmin2(bb1, __hadd2(o2, __hmin2(lb1, rb1)));
        }
        float nxt = (float)((off0 + 4) * (off0 + 4));
        __half2 m2 = __hmax2(__hmax2(ba0, bb0), __hmax2(ba1, bb1));
        float mb = fmaxf(__low2float(m2), __high2float(m2));
        if (!__any_sync(0xffffffffu, nxt < mb)) break;
    }

    float acc;
    {
        // row 0
        float b0 = __low2float(ba0), b1 = __high2float(ba0);
        float b2 = __low2float(bb0), b3 = __high2float(bb0);
        float n0 = fminf(fminf(b1, b2), b3);
        float n1 = fminf(fminf(b0, b2), b3);
        float n2 = fminf(fminf(b0, b1), b3);
        float n3 = fminf(fminf(b0, b1), b2);
        float mx = fmaxf(fmaxf(lx00, lx01), fmaxf(lx02, lx03));
        float e0 = __expf(lx00 - mx), e1 = __expf(lx01 - mx);
        float e2 = __expf(lx02 - mx), e3 = __expf(lx03 - mx);
        float s = e0 + e1 + e2 + e3;
        float d0 = (yv0 == 0) ? -fsqrt_fast(n0) : fsqrt_fast(b0);
        float d1 = (yv0 == 1) ? -fsqrt_fast(n1) : fsqrt_fast(b1);
        float d2 = (yv0 == 2) ? -fsqrt_fast(n2) : fsqrt_fast(b2);
        float d3 = (yv0 == 3) ? -fsqrt_fast(n3) : fsqrt_fast(b3);
        acc = __fdividef(e0 * d0 + e1 * d1 + e2 * d2 + e3 * d3, s);
    }
    {
        // row 1
        float b0 = __low2float(ba1), b1 = __high2float(ba1);
        float b2 = __low2float(bb1), b3 = __high2float(bb1);
        float n0 = fminf(fminf(b1, b2), b3);
        float n1 = fminf(fminf(b0, b2), b3);
        float n2 = fminf(fminf(b0, b1), b3);
        float n3 = fminf(fminf(b0, b1), b2);
        float mx = fmaxf(fmaxf(lx10, lx11), fmaxf(lx12, lx13));
        float e0 = __expf(lx10 - mx), e1 = __expf(lx11 - mx);
        float e2 = __expf(lx12 - mx), e3 = __expf(lx13 - mx);
        float s = e0 + e1 + e2 + e3;
        float d0 = (yv1 == 0) ? -fsqrt_fast(n0) : fsqrt_fast(b0);
        float d1 = (yv1 == 1) ? -fsqrt_fast(n1) : fsqrt_fast(b1);
        float d2 = (yv1 == 2) ? -fsqrt_fast(n2) : fsqrt_fast(b2);
        float d3 = (yv1 == 3) ? -fsqrt_fast(n3) : fsqrt_fast(b3);
        acc += __fdividef(e0 * d0 + e1 * d1 + e2 * d2 + e3 * d3, s);
    }

    // warp-shuffle reduction (fixed order -> deterministic)
    #pragma unroll
    for (int o = 16; o > 0; o >>= 1)
        acc += __shfl_down_sync(0xffffffffu, acc, o);

    __shared__ float swsum[8];
    if (lane == 0) swsum[wid] = acc;
    __syncthreads();

    if (wid == 0) {
        float v = (lane < 8) ? swsum[lane] : 0.0f;
        #pragma unroll
        for (int o = 4; o > 0; o >>= 1)
            v += __shfl_down_sync(0xffffffffu, v, o);

        if (lane == 0) {
            long long fx = llrintf(v * (float)FPSCALE);
            atomicAdd(&g_acc, (unsigned long long)fx);
            __threadfence();
            unsigned int done = atomicAdd(&g_count, 1u);
            if (done == NBLK2 - 1) {
                unsigned long long total = atomicAdd(&g_acc, 0ULL);
                out[0] = (float)((double)(long long)total / (FPSCALE * DENOM));
                g_acc = 0ULL;          // self-reset for next graph replay
                g_count = 0u;
                __threadfence();
            }
        }
    }
}

extern "C" void kernel_launch(void* const* d_in, const int* in_sizes, int n_in,
                              void* d_out, int out_size)
{
    const float* x;
    const int*   y;
    if (in_sizes[0] == NPIX * 4) {
        x = (const float*)d_in[0];
        y = (const int*)d_in[1];
    } else {
        x = (const float*)d_in[1];
        y = (const int*)d_in[0];
    }
    float* out = (float*)d_out;

    k_mask<<<256, 256>>>(y);
    k_horiz<<<NBLK2, 256>>>(x, y, out);
}

// round 16
// speedup vs baseline: 1.2661x; 1.2661x over previous
#include <cuda_runtime.h>
#include <cuda_fp16.h>
#include <math.h>

// Problem shape (fixed): B=8, C=4, H=256, W=256, labels in [0,4)
#define B 8
#define H 256
#define W 256
#define NPIX (B * H * W)          // 524288
#define NROWS (B * H)             // 2048
#define NBLK4 (NROWS / 4)         // 512 k_horiz blocks (4 rows each)
#define DENOM 2097152.0           // B*C*H*W
#define FPSCALE 16777216.0        // 2^24 fixed-point scale
#define HBIG 65504.0f             // half max: absent-class sentinel

// Scratch: per-pixel uint2 = two half2 = per-class vertical d^2 (half).
__device__ uint2 g_G[NPIX];
__device__ unsigned long long g_acc;         // fixed-point loss accumulator (zero-init)
__device__ unsigned int g_count;             // completed-block counter (zero-init)

__device__ __forceinline__ float fsqrt_fast(float v)
{
    float r;
    asm("sqrt.approx.f32 %0, %1;" : "=f"(r) : "f"(v));
    return r;
}

// ---------------------------------------------------------------------------
// K1: vertical EDT via per-column class bitmasks (round-10 version, measured
// 4.1 us). 256 blocks x 256 threads; 8 columns per block, 8 rows per thread.
// ---------------------------------------------------------------------------
__global__ void __launch_bounds__(256) k_vert(const int* __restrict__ y)
{
    __shared__ unsigned msk[4 * 8 * 8];      // [c][col][word] = c*64+col*8+word

    const int b    = blockIdx.x >> 5;        // 256 blocks: 8 b * 32 w-tiles
    const int w0   = (blockIdx.x & 31) << 3; // 8 columns per block
    const int tid  = threadIdx.x;            // 256 threads = 8 warps
    const int warp = tid >> 5;               // = mask word index (row/32)
    const int lane = tid & 31;

    // --- phase 1: build occupancy masks with ballots ---
    {
        const int row = warp * 32 + lane;
        const int* yrow = y + b * (H * W) + row * W + w0;
        int4 va = *(const int4*)yrow;
        int4 vb = *(const int4*)(yrow + 4);
        int lab[8] = {va.x, va.y, va.z, va.w, vb.x, vb.y, vb.z, vb.w};

        unsigned myword = 0;
        #pragma unroll
        for (int c = 0; c < 4; ++c) {
            #pragma unroll
            for (int k = 0; k < 8; ++k) {
                unsigned bal = __ballot_sync(0xffffffffu, lab[k] == c);
                if (lane == ((c << 3) | k)) myword = bal;
            }
        }
        msk[(lane >> 3) * 64 + (lane & 7) * 8 + warp] = myword;
    }
    __syncthreads();

    // --- phase 2: per-thread distance computation (8 rows x 1 col) ---
    const int col = tid & 7;
    const int h0  = (tid >> 3) << 3;         // 0,8,...,248
    const int wi  = h0 >> 5;                 // constant word for rows h0..h0+7
    const int hb  = h0 & 31;                 // 0,8,16,24

    unsigned resx[8], resy[8];
    float fa[8];

    #pragma unroll
    for (int c = 0; c < 4; ++c) {
        const unsigned* base = &msk[c * 64 + col * 8];
        const unsigned Mw = base[wi];

        // init_down: nearest set bit <= h0-1
        int last = -1000;
        {
            unsigned bits = hb ? (Mw & ((1u << hb) - 1u)) : 0u;
            if (bits) {
                last = wi * 32 + 31 - __clz(bits);
            } else {
                for (int wj = wi - 1; wj >= 0; --wj) {
                    unsigned m2 = base[wj];
                    if (m2) { last = wj * 32 + 31 - __clz(m2); break; }
                }
            }
        }
        // init_up: nearest set bit >= h0+8
        int nxt = 100000;
        {
            int rem = hb + 8;
            unsigned bits = (rem < 32) ? (Mw >> rem) : 0u;
            if (bits) {
                nxt = wi * 32 + rem + __ffs(bits) - 1;
            } else {
                for (int wj = wi + 1; wj < 8; ++wj) {
                    unsigned m2 = base[wj];
                    if (m2) { nxt = wj * 32 + __ffs(m2) - 1; break; }
                }
            }
        }

        int dd[8];
        #pragma unroll
        for (int i = 0; i < 8; ++i) {
            int h = h0 + i;
            if ((Mw >> (h & 31)) & 1u) last = h;
            dd[i] = h - last;
        }
        #pragma unroll
        for (int i = 7; i >= 0; --i) {
            int h = h0 + i;
            if ((Mw >> (h & 31)) & 1u) nxt = h;
            int du = nxt - h;
            int d = min(dd[i], du);
            float f = (d > 255) ? HBIG : (float)(d * d);
            if (c == 0)      fa[i] = f;
            else if (c == 1) {
                __half2 p = __floats2half2_rn(fa[i], f);
                resx[i] = *reinterpret_cast<unsigned*>(&p);
            }
            else if (c == 2) fa[i] = f;
            else {
                __half2 p = __floats2half2_rn(fa[i], f);
                resy[i] = *reinterpret_cast<unsigned*>(&p);
            }
        }
    }

    uint2* Gb = g_G + b * (H * W) + w0 + col;
    #pragma unroll
    for (int i = 0; i < 8; ++i)
        Gb[(h0 + i) * W] = make_uint2(resx[i], resy[i]);
}

// ---------------------------------------------------------------------------
// K2: horizontal min-plus, FOUR ROWS PER BLOCK. Offset loop, exit check,
// addressing, barriers and reduction shared across all 4 rows. Exit on max
// over 4 rows (extra offsets only add valid candidates -> still exact).
// ---------------------------------------------------------------------------
__global__ void __launch_bounds__(256) k_horiz(const float* __restrict__ x,
                                               const int* __restrict__ y,
                                               float* __restrict__ out)
{
    const int row0 = blockIdx.x * 4;   // rows row0..row0+3 (same image: 256%4==0)
    const int b    = row0 >> 8;
    const int h0r  = row0 & 255;
    const int tid  = threadIdx.x;      // 0..255, w = tid
    const int wid  = tid >> 5, lane = tid & 31;

    __shared__ uint2 sgp[4][768];      // per row: [pad 256][data 256][pad 256]

    // issue loads early — latency overlaps staging
    int   yv[4];
    float lx[4][4];
    const int base = (b * 4) * (H * W) + h0r * W + tid;
    #pragma unroll
    for (int r = 0; r < 4; ++r) {
        yv[r] = y[(row0 + r) * W + tid];
        #pragma unroll
        for (int c = 0; c < 4; ++c)
            lx[r][c] = x[base + r * W + c * (H * W)];
    }

    const uint2 big = make_uint2(0x7BFF7BFFu, 0x7BFF7BFFu);  // half2(65504) x2
    #pragma unroll
    for (int r = 0; r < 4; ++r) {
        sgp[r][tid] = big;                       // left pad
        sgp[r][512 + tid] = big;                 // right pad
        sgp[r][256 + tid] = g_G[(row0 + r) * W + tid];
    }
    __syncthreads();

    __half2 ba[4], bb[4];
    #pragma unroll
    for (int r = 0; r < 4; ++r) {
        uint2 q = sgp[r][256 + tid];
        ba[r] = *reinterpret_cast<__half2*>(&q.x);
        bb[r] = *reinterpret_cast<__half2*>(&q.y);
    }

    for (int off0 = 1; off0 < 256; off0 += 4) {
        #pragma unroll
        for (int u = 0; u < 4; ++u) {
            int off = off0 + u;                      // max 256 -> within pads
            __half2 o2 = __float2half2_rn((float)(off * off));
            #pragma unroll
            for (int r = 0; r < 4; ++r) {
                uint2 l = sgp[r][256 + tid - off];
                uint2 rr = sgp[r][256 + tid + off];
                __half2 la = *reinterpret_cast<__half2*>(&l.x);
                __half2 lb = *reinterpret_cast<__half2*>(&l.y);
                __half2 ra = *reinterpret_cast<__half2*>(&rr.x);
                __half2 rb = *reinterpret_cast<__half2*>(&rr.y);
                ba[r] = __hmin2(ba[r], __hadd2(o2, __hmin2(la, ra)));
                bb[r] = __hmin2(bb[r], __hadd2(o2, __hmin2(lb, rb)));
            }
        }
        float nxt = (float)((off0 + 4) * (off0 + 4));
        __half2 m2 = __hmax2(__hmax2(ba[0], bb[0]), __hmax2(ba[1], bb[1]));
        __half2 m3 = __hmax2(__hmax2(ba[2], bb[2]), __hmax2(ba[3], bb[3]));
        m2 = __hmax2(m2, m3);
        float mb = fmaxf(__low2float(m2), __high2float(m2));
        if (!__any_sync(0xffffffffu, nxt < mb)) break;
    }

    float acc = 0.0f;
    #pragma unroll
    for (int r = 0; r < 4; ++r) {
        float b0 = __low2float(ba[r]), b1 = __high2float(ba[r]);
        float b2 = __low2float(bb[r]), b3 = __high2float(bb[r]);
        float n0 = fminf(fminf(b1, b2), b3);
        float n1 = fminf(fminf(b0, b2), b3);
        float n2 = fminf(fminf(b0, b1), b3);
        float n3 = fminf(fminf(b0, b1), b2);
        float mx = fmaxf(fmaxf(lx[r][0], lx[r][1]), fmaxf(lx[r][2], lx[r][3]));
        float e0 = __expf(lx[r][0] - mx), e1 = __expf(lx[r][1] - mx);
        float e2 = __expf(lx[r][2] - mx), e3 = __expf(lx[r][3] - mx);
        float s = e0 + e1 + e2 + e3;
        float d0 = (yv[r] == 0) ? -fsqrt_fast(n0) : fsqrt_fast(b0);
        float d1 = (yv[r] == 1) ? -fsqrt_fast(n1) : fsqrt_fast(b1);
        float d2 = (yv[r] == 2) ? -fsqrt_fast(n2) : fsqrt_fast(b2);
        float d3 = (yv[r] == 3) ? -fsqrt_fast(n3) : fsqrt_fast(b3);
        acc += __fdividef(e0 * d0 + e1 * d1 + e2 * d2 + e3 * d3, s);
    }

    // warp-shuffle reduction (fixed order -> deterministic)
    #pragma unroll
    for (int o = 16; o > 0; o >>= 1)
        acc += __shfl_down_sync(0xffffffffu, acc, o);

    __shared__ float swsum[8];
    if (lane == 0) swsum[wid] = acc;
    __syncthreads();

    if (wid == 0) {
        float v = (lane < 8) ? swsum[lane] : 0.0f;
        #pragma unroll
        for (int o = 4; o > 0; o >>= 1)
            v += __shfl_down_sync(0xffffffffu, v, o);

        if (lane == 0) {
            long long fx = llrintf(v * (float)FPSCALE);
            atomicAdd(&g_acc, (unsigned long long)fx);
            __threadfence();
            unsigned int done = atomicAdd(&g_count, 1u);
            if (done == NBLK4 - 1) {
                unsigned long long total = atomicAdd(&g_acc, 0ULL);
                out[0] = (float)((double)(long long)total / (FPSCALE * DENOM));
                g_acc = 0ULL;          // self-reset for next graph replay
                g_count = 0u;
                __threadfence();
            }
        }
    }
}

extern "C" void kernel_launch(void* const* d_in, const int* in_sizes, int n_in,
                              void* d_out, int out_size)
{
    const float* x;
    const int*   y;
    if (in_sizes[0] == NPIX * 4) {
        x = (const float*)d_in[0];
        y = (const int*)d_in[1];
    } else {
        x = (const float*)d_in[1];
        y = (const int*)d_in[0];
    }
    float* out = (float*)d_out;

    k_vert<<<256, 256>>>(y);
    k_horiz<<<NBLK4, 256>>>(x, y, out);
}